// round 16
// baseline (speedup 1.0000x reference)
#include <cuda_runtime.h>
#include <cuda_bf16.h>
#include <cstdint>

#define BB 2
#define LL 384
#define DD 1280
#define HH 256
#define NB 10

// ---------------------------------------------------------------------------
// device globals (no allocation allowed)
// ---------------------------------------------------------------------------
__device__ __nv_bfloat16 g_xs[2][BB * LL * DD];        // x split hi/lo
__device__ __nv_bfloat16 g_ws[2][512 * DD];            // W^T split hi/lo
__device__ float g_pp[3 * BB * LL * 512];              // proj split-K partials
__device__ __nv_bfloat16 g_A[4][BB * LL * HH];         // xi: h+, l+, h-, l-
__device__ __nv_bfloat16 g_Bv[BB][4][LL * NB * HH];    // V variants

// ---------------------------------------------------------------------------
// helpers
// ---------------------------------------------------------------------------
__device__ __forceinline__ uint32_t smem_u32(const void* p) {
    uint32_t a;
    asm("{ .reg .u64 t; cvta.to.shared.u64 t, %1; cvt.u32.u64 %0, t; }"
        : "=r"(a) : "l"(p));
    return a;
}
__device__ __forceinline__ void ldsm_x4(uint32_t* r, uint32_t addr) {
    asm volatile("ldmatrix.sync.aligned.m8n8.x4.shared.b16 {%0,%1,%2,%3}, [%4];"
        : "=r"(r[0]), "=r"(r[1]), "=r"(r[2]), "=r"(r[3]) : "r"(addr));
}
__device__ __forceinline__ void ldsm_x2(uint32_t* r, uint32_t addr) {
    asm volatile("ldmatrix.sync.aligned.m8n8.x2.shared.b16 {%0,%1}, [%2];"
        : "=r"(r[0]), "=r"(r[1]) : "r"(addr));
}
__device__ __forceinline__ void mma16816(float* c, const uint32_t* a,
                                         const uint32_t* b) {
    asm volatile(
        "mma.sync.aligned.m16n8k16.row.col.f32.bf16.bf16.f32 "
        "{%0,%1,%2,%3}, {%4,%5,%6,%7}, {%8,%9}, {%0,%1,%2,%3};"
        : "+f"(c[0]), "+f"(c[1]), "+f"(c[2]), "+f"(c[3])
        : "r"(a[0]), "r"(a[1]), "r"(a[2]), "r"(a[3]), "r"(b[0]), "r"(b[1]));
}
__device__ __forceinline__ void cp16(uint32_t dst, const void* src) {
    asm volatile("cp.async.cg.shared.global [%0], [%1], 16;"
                 :: "r"(dst), "l"(src));
}
// mbarrier primitives
__device__ __forceinline__ void mbar_init(uint32_t addr, uint32_t cnt) {
    asm volatile("mbarrier.init.shared.b64 [%0], %1;"
                 :: "r"(addr), "r"(cnt) : "memory");
}
__device__ __forceinline__ void mbar_arrive(uint32_t addr) {
    asm volatile("mbarrier.arrive.shared.b64 _, [%0];"
                 :: "r"(addr) : "memory");
}
// .noinc is load-bearing: without it the async arrive first increments the
// pending count (net-zero on the phase) and the barrier NEVER completes.
__device__ __forceinline__ void cp_mbar_arrive_noinc(uint32_t addr) {
    asm volatile("cp.async.mbarrier.arrive.noinc.shared.b64 [%0];"
                 :: "r"(addr) : "memory");
}
__device__ __forceinline__ void mbar_wait(uint32_t addr, uint32_t parity) {
    asm volatile(
        "{\n\t.reg .pred P1;\n\tWL_%=:\n\t"
        "mbarrier.try_wait.parity.acquire.cta.shared::cta.b64 P1, [%0], %1;\n\t"
        "@!P1 bra WL_%=;\n\t}"
        :: "r"(addr), "r"(parity) : "memory");
}

// ---------------------------------------------------------------------------
// prep: fused  [blocks 0..959] split x into bf16 hi/lo (4 elem/thread)
//              [blocks 960..1599] transpose+split W -> g_ws
// ---------------------------------------------------------------------------
__global__ void prep_kernel(const float* __restrict__ x,
                            const float* __restrict__ Wi,
                            const float* __restrict__ Wj)
{
    if (blockIdx.x < 960) {
        const int t = blockIdx.x * 256 + threadIdx.x;
        const float4 v = *(const float4*)(x + t * 4);
        const float f[4] = {v.x, v.y, v.z, v.w};
        __nv_bfloat16 hi[4], lo[4];
        #pragma unroll
        for (int q = 0; q < 4; q++) {
            hi[q] = __float2bfloat16_rn(f[q]);
            lo[q] = __float2bfloat16_rn(f[q] - __bfloat162float(hi[q]));
        }
        *(uint2*)&g_xs[0][t * 4] = *(uint2*)hi;
        *(uint2*)&g_xs[1][t * 4] = *(uint2*)lo;
    } else {
        __shared__ float tile[32][33];
        const int wb = blockIdx.x - 960;
        const int n0 = (wb & 15) * 32;
        const int k0 = (wb >> 4) * 32;
        const int c  = threadIdx.x & 31;
        const int r0 = threadIdx.x >> 5;

        const bool second = (n0 >= HH);
        const float* __restrict__ W = second ? Wj : Wi;
        const int ncol = second ? (n0 - HH) : n0;

        #pragma unroll
        for (int p = 0; p < 4; p++) {
            const int r = r0 + p * 8;
            tile[r][c] = W[(k0 + r) * HH + ncol + c];
        }
        __syncthreads();
        #pragma unroll
        for (int p = 0; p < 4; p++) {
            const int r = r0 + p * 8;
            const float f = tile[c][r];
            const __nv_bfloat16 hi = __float2bfloat16_rn(f);
            const __nv_bfloat16 lo =
                __float2bfloat16_rn(f - __bfloat162float(hi));
            g_ws[0][(n0 + r) * DD + k0 + c] = hi;
            g_ws[1][(n0 + r) * DD + k0 + c] = lo;
        }
    }
}

// ---------------------------------------------------------------------------
// proj MMA: partial[kz] = x_split @ ws_split^T (3-chain bf16).
// CTA 128m x 64n, mbarrier ring, 1 CTA/SM (R14, unchanged).
// ---------------------------------------------------------------------------
#define PLDA 72
#define PJ_ABYTES (2 * 128 * PLDA * 2)      // 36864
#define PJ_BBYTES (2 * 64 * PLDA * 2)       // 18432
#define PJ_BUFB   (PJ_ABYTES + PJ_BBYTES)   // 55296
#define PJ_MBAR   (3 * PJ_BUFB)             // 165888
#define PJ_SMEM   (PJ_MBAR + 128)           // 166016

__global__ __launch_bounds__(256, 1) void proj_mma_kernel()
{
    extern __shared__ char dsm[];
    const uint32_t sbase = smem_u32(dsm);

    const int tid = threadIdx.x, wid = tid >> 5, lane = tid & 31;
    const int m0 = blockIdx.x * 128;        // over 768
    const int n0 = blockIdx.y * 64;         // over 512
    const int kz = blockIdx.z;
    const int c0 = kz * 7;
    const int nc = (kz == 2) ? 6 : 7;

    const int m_off = (wid & 3) * 32;
    const int n_off = (wid >> 2) * 32;

    const int a_r = lane & 15;
    const int a_c = (lane >> 4) << 3;
    const int b_r = (lane & 7) + ((lane & 16) ? 8 : 0);
    const int b_c = (lane & 8) ? 8 : 0;

    const uint32_t mb = sbase + PJ_MBAR;     // full[s]=mb+s*16, empty=+8

    auto stage_cp = [&](int q) {
        const int kg = (c0 + q) * 64;
        const uint32_t bufA = sbase + (q % 3) * PJ_BUFB;
        const uint32_t bufB = bufA + PJ_ABYTES;
        #pragma unroll
        for (int it = 0; it < 8; it++) {
            const int i = tid + it * 256;
            const int var = i >> 10;
            const int row = (i >> 3) & 127;
            const int g   = i & 7;
            cp16(bufA + (var * 128 + row) * (PLDA * 2) + g * 16,
                 g_xs[var] + (m0 + row) * DD + kg + g * 8);
        }
        #pragma unroll
        for (int it = 0; it < 4; it++) {
            const int i = tid + it * 256;
            const int var = i >> 9;
            const int row = (i >> 3) & 63;
            const int g   = i & 7;
            cp16(bufB + (var * 64 + row) * (PLDA * 2) + g * 16,
                 g_ws[var] + (n0 + row) * DD + kg + g * 8);
        }
    };

    if (tid < 3) {
        mbar_init(mb + tid * 16, 256);       // full[tid]
        mbar_init(mb + tid * 16 + 8, 8);     // empty[tid]
    }
    __syncthreads();

    #pragma unroll
    for (int c = 0; c < 3; c++) {
        stage_cp(c);
        cp_mbar_arrive_noinc(mb + c * 16);
    }

    float acc[2][4][4] = {};   // [mt][n8-tile][frag]

    for (int q = 0; q < nc; q++) {
        const int s = q % 3;
        const uint32_t par = (uint32_t)((q / 3) & 1);

        mbar_wait(mb + s * 16, par);

        const uint32_t bufA = sbase + s * PJ_BUFB;
        const uint32_t bufB = bufA + PJ_ABYTES;

        #pragma unroll
        for (int ks = 0; ks < 4; ks++) {
            uint32_t ah[2][4], al[2][4];
            #pragma unroll
            for (int mt = 0; mt < 2; mt++) {
                const uint32_t row = m_off + mt * 16 + a_r;
                const uint32_t col = ks * 16 + a_c;
                ldsm_x4(ah[mt], bufA + (row * PLDA + col) * 2);
                ldsm_x4(al[mt], bufA + ((128 + row) * PLDA + col) * 2);
            }
            uint32_t bh[2][4], bl[2][4];
            #pragma unroll
            for (int np = 0; np < 2; np++) {
                const uint32_t row = n_off + np * 16 + b_r;
                const uint32_t col = ks * 16 + b_c;
                ldsm_x4(bh[np], bufB + (row * PLDA + col) * 2);
                ldsm_x4(bl[np], bufB + ((64 + row) * PLDA + col) * 2);
            }
            #pragma unroll
            for (int mt = 0; mt < 2; mt++)
                #pragma unroll
                for (int np = 0; np < 2; np++)
                    #pragma unroll
                    for (int nt = 0; nt < 2; nt++)
                        mma16816(acc[mt][np * 2 + nt], ah[mt],
                                 bh[np] + nt * 2);
            #pragma unroll
            for (int mt = 0; mt < 2; mt++)
                #pragma unroll
                for (int np = 0; np < 2; np++)
                    #pragma unroll
                    for (int nt = 0; nt < 2; nt++)
                        mma16816(acc[mt][np * 2 + nt], ah[mt],
                                 bl[np] + nt * 2);
            #pragma unroll
            for (int mt = 0; mt < 2; mt++)
                #pragma unroll
                for (int np = 0; np < 2; np++)
                    #pragma unroll
                    for (int nt = 0; nt < 2; nt++)
                        mma16816(acc[mt][np * 2 + nt], al[mt],
                                 bh[np] + nt * 2);
        }

        if (lane == 0) mbar_arrive(mb + s * 16 + 8);

        if (q + 3 < nc) {
            mbar_wait(mb + s * 16 + 8, par);
            stage_cp(q + 3);
            cp_mbar_arrive_noinc(mb + s * 16);
        }
    }

    const int tg = lane >> 2, tig = lane & 3;
    float* pp = g_pp + (size_t)kz * (BB * LL * 512);
    #pragma unroll
    for (int mt = 0; mt < 2; mt++) {
        #pragma unroll
        for (int np = 0; np < 2; np++) {
            #pragma unroll
            for (int nt = 0; nt < 2; nt++) {
                const int col = n0 + n_off + np * 16 + nt * 8 + tig * 2;
                const int row = m0 + m_off + mt * 16 + tg;
                const float* c = acc[mt][np * 2 + nt];
                *(float2*)&pp[(size_t)row * 512 + col] =
                    make_float2(c[0], c[1]);
                *(float2*)&pp[(size_t)(row + 8) * 512 + col] =
                    make_float2(c[2], c[3]);
            }
        }
    }
}

// ---------------------------------------------------------------------------
// postproj (fused): xi split + V build per row r
// ---------------------------------------------------------------------------
#define SLAB (BB * LL * 512)

__global__ __launch_bounds__(256) void postproj_kernel(
    const float* __restrict__ bi, const float* __restrict__ bj,
    const float* __restrict__ Wo)
{
    const int r = blockIdx.x;              // 0..767
    const int b = r / LL;
    const int j = r % LL;
    const int t = threadIdx.x;

    {
        const size_t o = (size_t)r * 512 + t;
        const float f = g_pp[o] + g_pp[o + SLAB] + g_pp[o + 2 * SLAB] + bi[t];
        const float p = fmaxf(f, 0.f);
        const float m = fminf(f, 0.f);
        const __nv_bfloat16 ph = __float2bfloat16_rn(p);
        const __nv_bfloat16 pl =
            __float2bfloat16_rn(p - __bfloat162float(ph));
        const __nv_bfloat16 mh = __float2bfloat16_rn(m);
        const __nv_bfloat16 ml =
            __float2bfloat16_rn(m - __bfloat162float(mh));
        const int idx = r * HH + t;
        g_A[0][idx] = ph; g_A[1][idx] = pl;
        g_A[2][idx] = mh; g_A[3][idx] = ml;
    }

    const int half = t >> 7;
    const int k0   = (t & 127) * 2;

    const size_t o = (size_t)r * 512 + 256 + k0;
    const float f0 = g_pp[o] + g_pp[o + SLAB] + g_pp[o + 2 * SLAB] + bj[k0];
    const float f1 = g_pp[o + 1] + g_pp[o + 1 + SLAB]
                   + g_pp[o + 1 + 2 * SLAB] + bj[k0 + 1];
    const float p0 = fmaxf(f0, 0.f), m0v = fminf(f0, 0.f);
    const float p1 = fmaxf(f1, 0.f), m1v = fminf(f1, 0.f);

    #pragma unroll
    for (int q = 0; q < 5; q++) {
        const int n = half * 5 + q;
        const float w0 = Wo[k0 * NB + n];
        const float w1 = Wo[(k0 + 1) * NB + n];

        const float vp0 = p0 * w0,  vp1 = p1 * w1;
        const float vm0 = m0v * w0, vm1 = m1v * w1;

        const __nv_bfloat162 ph = __floats2bfloat162_rn(vp0, vp1);
        const __nv_bfloat162 pl = __floats2bfloat162_rn(
            vp0 - __low2float(ph), vp1 - __high2float(ph));
        const __nv_bfloat162 mh = __floats2bfloat162_rn(vm0, vm1);
        const __nv_bfloat162 ml = __floats2bfloat162_rn(
            vm0 - __low2float(mh), vm1 - __high2float(mh));

        const size_t idx = (size_t)(j * NB + n) * HH + k0;
        *(__nv_bfloat162*)&g_Bv[b][0][idx] = ph;
        *(__nv_bfloat162*)&g_Bv[b][1][idx] = pl;
        *(__nv_bfloat162*)&g_Bv[b][2][idx] = mh;
        *(__nv_bfloat162*)&g_Bv[b][3][idx] = ml;
    }
}

// ---------------------------------------------------------------------------
// pair MMA: CTA tile 128m x 160n, 512 threads, 16 warps as 4m x 4n,
// warp tile 32m x 40n (acc 40 regs). 1 CTA/SM, grid 24x6 = 144 = one wave.
// mbarrier ring (R12 protocol): full=512 noinc arrivals, empty=16 warps.
// K = 2 signs x 256 in 16 chunks of 32.
// ---------------------------------------------------------------------------
#define PTHREADS 512
#define TN 160
#define KLDA 40
#define P_ABYTES (2 * 128 * KLDA * 2)      // 20480
#define P_BBYTES (2 * TN * KLDA * 2)       // 25600
#define P_BUFB   (P_ABYTES + P_BBYTES)     // 46080
#define MBAR_OFF (3 * P_BUFB)              // 138240
#define PAIR_SMEM (MBAR_OFF + 128)         // 138368

__global__ __launch_bounds__(PTHREADS, 1) void pair_mma_kernel(
    const float* __restrict__ bo, float* __restrict__ out)
{
    extern __shared__ char dsm[];
    const uint32_t sbase = smem_u32(dsm);

    const int tid = threadIdx.x, wid = tid >> 5, lane = tid & 31;
    const int n0 = blockIdx.x * TN;          // over 3840
    const int m0 = blockIdx.y * 128;         // over 768
    const int b  = (m0 >= LL) ? 1 : 0;
    const int m_off = (wid & 3) * 32;        // 4 m-groups x 32
    const int n_off = (wid >> 2) * 40;       // 4 n-groups x 40

    const int a_r = lane & 15;
    const int a_c = (lane >> 4) << 3;
    const int b_r = (lane & 7) + ((lane & 16) ? 8 : 0);
    const int b_c = (lane & 8) ? 8 : 0;
    const int b2_r = lane & 7;
    const int b2_c = (lane & 8) ? 8 : 0;

    const uint32_t mb = sbase + MBAR_OFF;    // full[s]=mb+s*16, empty=+8

    auto stage_cp = [&](int ch) {
        const int sign = ch >> 3;
        const int kb   = (ch & 7) * 32;
        const uint32_t bufA = sbase + (ch % 3) * P_BUFB;
        const uint32_t bufB = bufA + P_ABYTES;
        // A: 2var x 128 rows x 4 granules = 1024 (2/thread, exact)
        #pragma unroll
        for (int it = 0; it < 2; it++) {
            const int i = tid + it * PTHREADS;
            const int var = i >> 9;
            const int row = (i >> 2) & 127;
            const int g   = i & 3;
            cp16(bufA + (var * 128 + row) * (KLDA * 2) + g * 16,
                 g_A[sign * 2 + var] + (m0 + row) * HH + kb + g * 8);
        }
        // B: 2var x 160 rows x 4 granules = 1280 (2.5/thread, guarded)
        #pragma unroll
        for (int it = 0; it < 3; it++) {
            const int i = tid + it * PTHREADS;
            if (i < 2 * TN * 4) {
                const int var = (i >= TN * 4) ? 1 : 0;
                const int jx  = i - var * TN * 4;
                const int row = jx >> 2;
                const int g   = jx & 3;
                cp16(bufB + (var * TN + row) * (KLDA * 2) + g * 16,
                     g_Bv[b][sign * 2 + var] + (n0 + row) * HH + kb + g * 8);
            }
        }
    };

    if (tid < 3) {
        mbar_init(mb + tid * 16, PTHREADS);  // full[tid]
        mbar_init(mb + tid * 16 + 8, 16);    // empty[tid]
    }
    __syncthreads();

    #pragma unroll
    for (int c = 0; c < 3; c++) {
        stage_cp(c);
        cp_mbar_arrive_noinc(mb + c * 16);
    }

    float acc[2][5][4] = {};   // [mt][n8-tile 0..4][frag]

    for (int ch = 0; ch < 16; ch++) {
        const int s = ch % 3;
        const uint32_t par = (uint32_t)((ch / 3) & 1);

        mbar_wait(mb + s * 16, par);

        const uint32_t bufA = sbase + s * P_BUFB;
        const uint32_t bufB = bufA + P_ABYTES;

        #pragma unroll
        for (int ks = 0; ks < 2; ks++) {
            uint32_t ah[2][4], al[2][4];
            #pragma unroll
            for (int mt = 0; mt < 2; mt++) {
                const uint32_t row = m_off + mt * 16 + a_r;
                const uint32_t col = ks * 16 + a_c;
                ldsm_x4(ah[mt], bufA + (row * KLDA + col) * 2);
                ldsm_x4(al[mt], bufA + ((128 + row) * KLDA + col) * 2);
            }
            uint32_t bh[2][4], bl[2][4], b2h[2], b2l[2];
            #pragma unroll
            for (int np = 0; np < 2; np++) {
                const uint32_t row = n_off + np * 16 + b_r;
                const uint32_t col = ks * 16 + b_c;
                ldsm_x4(bh[np], bufB + (row * KLDA + col) * 2);
                ldsm_x4(bl[np], bufB + ((TN + row) * KLDA + col) * 2);
            }
            {
                const uint32_t row = n_off + 32 + b2_r;
                const uint32_t col = ks * 16 + b2_c;
                ldsm_x2(b2h, bufB + (row * KLDA + col) * 2);
                ldsm_x2(b2l, bufB + ((TN + row) * KLDA + col) * 2);
            }
            // term-major: 10 independent accs between same-acc reuses
            #pragma unroll
            for (int mt = 0; mt < 2; mt++) {
                #pragma unroll
                for (int np = 0; np < 2; np++)
                    #pragma unroll
                    for (int nt = 0; nt < 2; nt++)
                        mma16816(acc[mt][np * 2 + nt], ah[mt],
                                 bh[np] + nt * 2);
                mma16816(acc[mt][4], ah[mt], b2h);
            }
            #pragma unroll
            for (int mt = 0; mt < 2; mt++) {
                #pragma unroll
                for (int np = 0; np < 2; np++)
                    #pragma unroll
                    for (int nt = 0; nt < 2; nt++)
                        mma16816(acc[mt][np * 2 + nt], ah[mt],
                                 bl[np] + nt * 2);
                mma16816(acc[mt][4], ah[mt], b2l);
            }
            #pragma unroll
            for (int mt = 0; mt < 2; mt++) {
                #pragma unroll
                for (int np = 0; np < 2; np++)
                    #pragma unroll
                    for (int nt = 0; nt < 2; nt++)
                        mma16816(acc[mt][np * 2 + nt], al[mt],
                                 bh[np] + nt * 2);
                mma16816(acc[mt][4], al[mt], b2h);
            }
        }

        if (lane == 0) mbar_arrive(mb + s * 16 + 8);

        if (ch + 3 < 16) {
            mbar_wait(mb + s * 16 + 8, par);
            stage_cp(ch + 3);
            cp_mbar_arrive_noinc(mb + s * 16);
        }
    }

    const int tg = lane >> 2, tig = lane & 3;
    #pragma unroll
    for (int mt = 0; mt < 2; mt++) {
        #pragma unroll
        for (int q = 0; q < 5; q++) {
            const int ncol = n0 + n_off + q * 8 + tig * 2;
            const int bin = ncol % NB;
            const float b0v = bo[bin];
            const float b1v = bo[bin + 1];
            const float* c = acc[mt][q];
            const int m = m0 + m_off + mt * 16 + tg;
            float* p0 = out + (size_t)m * (LL * NB) + ncol;
            *(float2*)p0 = make_float2(c[0] + b0v, c[1] + b1v);
            float* p1 = p0 + 8 * (size_t)(LL * NB);
            *(float2*)p1 = make_float2(c[2] + b0v, c[3] + b1v);
        }
    }
}

// ---------------------------------------------------------------------------
// launch
// ---------------------------------------------------------------------------
extern "C" void kernel_launch(void* const* d_in, const int* in_sizes, int n_in,
                              void* d_out, int out_size)
{
    const float* x  = (const float*)d_in[0];
    const float* Wi = (const float*)d_in[1];
    const float* bi = (const float*)d_in[2];
    const float* Wj = (const float*)d_in[3];
    const float* bj = (const float*)d_in[4];
    const float* Wo = (const float*)d_in[5];
    const float* bo = (const float*)d_in[6];
    float* out = (float*)d_out;

    prep_kernel<<<1600, 256>>>(x, Wi, Wj);

    cudaFuncSetAttribute(proj_mma_kernel,
                         cudaFuncAttributeMaxDynamicSharedMemorySize, PJ_SMEM);
    dim3 gA(6, 8, 3);
    proj_mma_kernel<<<gA, 256, PJ_SMEM>>>();

    postproj_kernel<<<768, 256>>>(bi, bj, Wo);

    cudaFuncSetAttribute(pair_mma_kernel,
                         cudaFuncAttributeMaxDynamicSharedMemorySize, PAIR_SMEM);
    dim3 gP(3840 / TN, 6);
    pair_mma_kernel<<<gP, PTHREADS, PAIR_SMEM>>>(bo, out);
}

// round 17
// speedup vs baseline: 1.0794x; 1.0794x over previous
#include <cuda_runtime.h>
#include <cuda_bf16.h>
#include <cstdint>

#define BB 2
#define LL 384
#define DD 1280
#define HH 256
#define NB 10

// ---------------------------------------------------------------------------
// device globals (no allocation allowed)
// ---------------------------------------------------------------------------
__device__ __nv_bfloat16 g_xs[2][BB * LL * DD];        // x split hi/lo
__device__ __nv_bfloat16 g_ws[2][512 * DD];            // W^T split hi/lo
__device__ float g_pp[3 * BB * LL * 512];              // proj split-K partials
__device__ __nv_bfloat16 g_A[4][BB * LL * HH];         // xi: h+, l+, h-, l-
__device__ __nv_bfloat16 g_Bv[BB][4][LL * NB * HH];    // V variants

// ---------------------------------------------------------------------------
// helpers
// ---------------------------------------------------------------------------
__device__ __forceinline__ uint32_t smem_u32(const void* p) {
    uint32_t a;
    asm("{ .reg .u64 t; cvta.to.shared.u64 t, %1; cvt.u32.u64 %0, t; }"
        : "=r"(a) : "l"(p));
    return a;
}
__device__ __forceinline__ void ldsm_x4(uint32_t* r, uint32_t addr) {
    asm volatile("ldmatrix.sync.aligned.m8n8.x4.shared.b16 {%0,%1,%2,%3}, [%4];"
        : "=r"(r[0]), "=r"(r[1]), "=r"(r[2]), "=r"(r[3]) : "r"(addr));
}
__device__ __forceinline__ void ldsm_x2(uint32_t* r, uint32_t addr) {
    asm volatile("ldmatrix.sync.aligned.m8n8.x2.shared.b16 {%0,%1}, [%2];"
        : "=r"(r[0]), "=r"(r[1]) : "r"(addr));
}
__device__ __forceinline__ void mma16816(float* c, const uint32_t* a,
                                         const uint32_t* b) {
    asm volatile(
        "mma.sync.aligned.m16n8k16.row.col.f32.bf16.bf16.f32 "
        "{%0,%1,%2,%3}, {%4,%5,%6,%7}, {%8,%9}, {%0,%1,%2,%3};"
        : "+f"(c[0]), "+f"(c[1]), "+f"(c[2]), "+f"(c[3])
        : "r"(a[0]), "r"(a[1]), "r"(a[2]), "r"(a[3]), "r"(b[0]), "r"(b[1]));
}
__device__ __forceinline__ void cp16(uint32_t dst, const void* src) {
    asm volatile("cp.async.cg.shared.global [%0], [%1], 16;"
                 :: "r"(dst), "l"(src));
}
// mbarrier primitives
__device__ __forceinline__ void mbar_init(uint32_t addr, uint32_t cnt) {
    asm volatile("mbarrier.init.shared.b64 [%0], %1;"
                 :: "r"(addr), "r"(cnt) : "memory");
}
__device__ __forceinline__ void mbar_arrive(uint32_t addr) {
    asm volatile("mbarrier.arrive.shared.b64 _, [%0];"
                 :: "r"(addr) : "memory");
}
// .noinc is load-bearing: without it the async arrive first increments the
// pending count (net-zero on the phase) and the barrier NEVER completes.
__device__ __forceinline__ void cp_mbar_arrive_noinc(uint32_t addr) {
    asm volatile("cp.async.mbarrier.arrive.noinc.shared.b64 [%0];"
                 :: "r"(addr) : "memory");
}
__device__ __forceinline__ void mbar_wait(uint32_t addr, uint32_t parity) {
    asm volatile(
        "{\n\t.reg .pred P1;\n\tWL_%=:\n\t"
        "mbarrier.try_wait.parity.acquire.cta.shared::cta.b64 P1, [%0], %1;\n\t"
        "@!P1 bra WL_%=;\n\t}"
        :: "r"(addr), "r"(parity) : "memory");
}

// ---------------------------------------------------------------------------
// prep: fused  [blocks 0..959] split x into bf16 hi/lo (4 elem/thread)
//              [blocks 960..1599] transpose+split W -> g_ws
// ---------------------------------------------------------------------------
__global__ void prep_kernel(const float* __restrict__ x,
                            const float* __restrict__ Wi,
                            const float* __restrict__ Wj)
{
    if (blockIdx.x < 960) {
        const int t = blockIdx.x * 256 + threadIdx.x;
        const float4 v = *(const float4*)(x + t * 4);
        const float f[4] = {v.x, v.y, v.z, v.w};
        __nv_bfloat16 hi[4], lo[4];
        #pragma unroll
        for (int q = 0; q < 4; q++) {
            hi[q] = __float2bfloat16_rn(f[q]);
            lo[q] = __float2bfloat16_rn(f[q] - __bfloat162float(hi[q]));
        }
        *(uint2*)&g_xs[0][t * 4] = *(uint2*)hi;
        *(uint2*)&g_xs[1][t * 4] = *(uint2*)lo;
    } else {
        __shared__ float tile[32][33];
        const int wb = blockIdx.x - 960;
        const int n0 = (wb & 15) * 32;
        const int k0 = (wb >> 4) * 32;
        const int c  = threadIdx.x & 31;
        const int r0 = threadIdx.x >> 5;

        const bool second = (n0 >= HH);
        const float* __restrict__ W = second ? Wj : Wi;
        const int ncol = second ? (n0 - HH) : n0;

        #pragma unroll
        for (int p = 0; p < 4; p++) {
            const int r = r0 + p * 8;
            tile[r][c] = W[(k0 + r) * HH + ncol + c];
        }
        __syncthreads();
        #pragma unroll
        for (int p = 0; p < 4; p++) {
            const int r = r0 + p * 8;
            const float f = tile[c][r];
            const __nv_bfloat16 hi = __float2bfloat16_rn(f);
            const __nv_bfloat16 lo =
                __float2bfloat16_rn(f - __bfloat162float(hi));
            g_ws[0][(n0 + r) * DD + k0 + c] = hi;
            g_ws[1][(n0 + r) * DD + k0 + c] = lo;
        }
    }
}

// ---------------------------------------------------------------------------
// proj MMA: partial[kz] = x_split @ ws_split^T (3-chain bf16).
// CTA 128m x 64n, mbarrier ring, 1 CTA/SM (R14, unchanged).
// ---------------------------------------------------------------------------
#define PLDA 72
#define PJ_ABYTES (2 * 128 * PLDA * 2)      // 36864
#define PJ_BBYTES (2 * 64 * PLDA * 2)       // 18432
#define PJ_BUFB   (PJ_ABYTES + PJ_BBYTES)   // 55296
#define PJ_MBAR   (3 * PJ_BUFB)             // 165888
#define PJ_SMEM   (PJ_MBAR + 128)           // 166016

__global__ __launch_bounds__(256, 1) void proj_mma_kernel()
{
    extern __shared__ char dsm[];
    const uint32_t sbase = smem_u32(dsm);

    const int tid = threadIdx.x, wid = tid >> 5, lane = tid & 31;
    const int m0 = blockIdx.x * 128;        // over 768
    const int n0 = blockIdx.y * 64;         // over 512
    const int kz = blockIdx.z;
    const int c0 = kz * 7;
    const int nc = (kz == 2) ? 6 : 7;

    const int m_off = (wid & 3) * 32;
    const int n_off = (wid >> 2) * 32;

    const int a_r = lane & 15;
    const int a_c = (lane >> 4) << 3;
    const int b_r = (lane & 7) + ((lane & 16) ? 8 : 0);
    const int b_c = (lane & 8) ? 8 : 0;

    const uint32_t mb = sbase + PJ_MBAR;     // full[s]=mb+s*16, empty=+8

    auto stage_cp = [&](int q) {
        const int kg = (c0 + q) * 64;
        const uint32_t bufA = sbase + (q % 3) * PJ_BUFB;
        const uint32_t bufB = bufA + PJ_ABYTES;
        #pragma unroll
        for (int it = 0; it < 8; it++) {
            const int i = tid + it * 256;
            const int var = i >> 10;
            const int row = (i >> 3) & 127;
            const int g   = i & 7;
            cp16(bufA + (var * 128 + row) * (PLDA * 2) + g * 16,
                 g_xs[var] + (m0 + row) * DD + kg + g * 8);
        }
        #pragma unroll
        for (int it = 0; it < 4; it++) {
            const int i = tid + it * 256;
            const int var = i >> 9;
            const int row = (i >> 3) & 63;
            const int g   = i & 7;
            cp16(bufB + (var * 64 + row) * (PLDA * 2) + g * 16,
                 g_ws[var] + (n0 + row) * DD + kg + g * 8);
        }
    };

    if (tid < 3) {
        mbar_init(mb + tid * 16, 256);       // full[tid]
        mbar_init(mb + tid * 16 + 8, 8);     // empty[tid]
    }
    __syncthreads();

    #pragma unroll
    for (int c = 0; c < 3; c++) {
        stage_cp(c);
        cp_mbar_arrive_noinc(mb + c * 16);
    }

    float acc[2][4][4] = {};   // [mt][n8-tile][frag]

    for (int q = 0; q < nc; q++) {
        const int s = q % 3;
        const uint32_t par = (uint32_t)((q / 3) & 1);

        mbar_wait(mb + s * 16, par);

        const uint32_t bufA = sbase + s * PJ_BUFB;
        const uint32_t bufB = bufA + PJ_ABYTES;

        #pragma unroll
        for (int ks = 0; ks < 4; ks++) {
            uint32_t ah[2][4], al[2][4];
            #pragma unroll
            for (int mt = 0; mt < 2; mt++) {
                const uint32_t row = m_off + mt * 16 + a_r;
                const uint32_t col = ks * 16 + a_c;
                ldsm_x4(ah[mt], bufA + (row * PLDA + col) * 2);
                ldsm_x4(al[mt], bufA + ((128 + row) * PLDA + col) * 2);
            }
            uint32_t bh[2][4], bl[2][4];
            #pragma unroll
            for (int np = 0; np < 2; np++) {
                const uint32_t row = n_off + np * 16 + b_r;
                const uint32_t col = ks * 16 + b_c;
                ldsm_x4(bh[np], bufB + (row * PLDA + col) * 2);
                ldsm_x4(bl[np], bufB + ((64 + row) * PLDA + col) * 2);
            }
            #pragma unroll
            for (int mt = 0; mt < 2; mt++)
                #pragma unroll
                for (int np = 0; np < 2; np++)
                    #pragma unroll
                    for (int nt = 0; nt < 2; nt++)
                        mma16816(acc[mt][np * 2 + nt], ah[mt],
                                 bh[np] + nt * 2);
            #pragma unroll
            for (int mt = 0; mt < 2; mt++)
                #pragma unroll
                for (int np = 0; np < 2; np++)
                    #pragma unroll
                    for (int nt = 0; nt < 2; nt++)
                        mma16816(acc[mt][np * 2 + nt], ah[mt],
                                 bl[np] + nt * 2);
            #pragma unroll
            for (int mt = 0; mt < 2; mt++)
                #pragma unroll
                for (int np = 0; np < 2; np++)
                    #pragma unroll
                    for (int nt = 0; nt < 2; nt++)
                        mma16816(acc[mt][np * 2 + nt], al[mt],
                                 bh[np] + nt * 2);
        }

        if (lane == 0) mbar_arrive(mb + s * 16 + 8);

        if (q + 3 < nc) {
            mbar_wait(mb + s * 16 + 8, par);
            stage_cp(q + 3);
            cp_mbar_arrive_noinc(mb + s * 16);
        }
    }

    const int tg = lane >> 2, tig = lane & 3;
    float* pp = g_pp + (size_t)kz * (BB * LL * 512);
    #pragma unroll
    for (int mt = 0; mt < 2; mt++) {
        #pragma unroll
        for (int np = 0; np < 2; np++) {
            #pragma unroll
            for (int nt = 0; nt < 2; nt++) {
                const int col = n0 + n_off + np * 16 + nt * 8 + tig * 2;
                const int row = m0 + m_off + mt * 16 + tg;
                const float* c = acc[mt][np * 2 + nt];
                *(float2*)&pp[(size_t)row * 512 + col] =
                    make_float2(c[0], c[1]);
                *(float2*)&pp[(size_t)(row + 8) * 512 + col] =
                    make_float2(c[2], c[3]);
            }
        }
    }
}

// ---------------------------------------------------------------------------
// postproj (fused): xi split + V build per row r
// ---------------------------------------------------------------------------
#define SLAB (BB * LL * 512)

__global__ __launch_bounds__(256) void postproj_kernel(
    const float* __restrict__ bi, const float* __restrict__ bj,
    const float* __restrict__ Wo)
{
    const int r = blockIdx.x;              // 0..767
    const int b = r / LL;
    const int j = r % LL;
    const int t = threadIdx.x;

    {
        const size_t o = (size_t)r * 512 + t;
        const float f = g_pp[o] + g_pp[o + SLAB] + g_pp[o + 2 * SLAB] + bi[t];
        const float p = fmaxf(f, 0.f);
        const float m = fminf(f, 0.f);
        const __nv_bfloat16 ph = __float2bfloat16_rn(p);
        const __nv_bfloat16 pl =
            __float2bfloat16_rn(p - __bfloat162float(ph));
        const __nv_bfloat16 mh = __float2bfloat16_rn(m);
        const __nv_bfloat16 ml =
            __float2bfloat16_rn(m - __bfloat162float(mh));
        const int idx = r * HH + t;
        g_A[0][idx] = ph; g_A[1][idx] = pl;
        g_A[2][idx] = mh; g_A[3][idx] = ml;
    }

    const int half = t >> 7;
    const int k0   = (t & 127) * 2;

    const size_t o = (size_t)r * 512 + 256 + k0;
    const float f0 = g_pp[o] + g_pp[o + SLAB] + g_pp[o + 2 * SLAB] + bj[k0];
    const float f1 = g_pp[o + 1] + g_pp[o + 1 + SLAB]
                   + g_pp[o + 1 + 2 * SLAB] + bj[k0 + 1];
    const float p0 = fmaxf(f0, 0.f), m0v = fminf(f0, 0.f);
    const float p1 = fmaxf(f1, 0.f), m1v = fminf(f1, 0.f);

    #pragma unroll
    for (int q = 0; q < 5; q++) {
        const int n = half * 5 + q;
        const float w0 = Wo[k0 * NB + n];
        const float w1 = Wo[(k0 + 1) * NB + n];

        const float vp0 = p0 * w0,  vp1 = p1 * w1;
        const float vm0 = m0v * w0, vm1 = m1v * w1;

        const __nv_bfloat162 ph = __floats2bfloat162_rn(vp0, vp1);
        const __nv_bfloat162 pl = __floats2bfloat162_rn(
            vp0 - __low2float(ph), vp1 - __high2float(ph));
        const __nv_bfloat162 mh = __floats2bfloat162_rn(vm0, vm1);
        const __nv_bfloat162 ml = __floats2bfloat162_rn(
            vm0 - __low2float(mh), vm1 - __high2float(mh));

        const size_t idx = (size_t)(j * NB + n) * HH + k0;
        *(__nv_bfloat162*)&g_Bv[b][0][idx] = ph;
        *(__nv_bfloat162*)&g_Bv[b][1][idx] = pl;
        *(__nv_bfloat162*)&g_Bv[b][2][idx] = mh;
        *(__nv_bfloat162*)&g_Bv[b][3][idx] = ml;
    }
}

// ---------------------------------------------------------------------------
// pair MMA: CTA tile 128m x 160n, 8 warps as 2m x 4n, warp tile 64m x 40n
// (R15 config) with KC=64 chunks: K = 2 signs x 256 in 8 chunks of 64.
// 2-slot mbarrier ring (skew bound 2 chunks). 1 CTA/SM, grid 144 = one wave.
// ---------------------------------------------------------------------------
#define TN 160
#define KLDA 72
#define P_ABYTES (2 * 128 * KLDA * 2)      // 36864
#define P_BBYTES (2 * TN * KLDA * 2)       // 46080
#define P_BUFB   (P_ABYTES + P_BBYTES)     // 82944
#define MBAR_OFF (2 * P_BUFB)              // 165888
#define PAIR_SMEM (MBAR_OFF + 128)         // 166016

__global__ __launch_bounds__(256, 1) void pair_mma_kernel(
    const float* __restrict__ bo, float* __restrict__ out)
{
    extern __shared__ char dsm[];
    const uint32_t sbase = smem_u32(dsm);

    const int tid = threadIdx.x, wid = tid >> 5, lane = tid & 31;
    const int n0 = blockIdx.x * TN;          // over 3840
    const int m0 = blockIdx.y * 128;         // over 768
    const int b  = (m0 >= LL) ? 1 : 0;
    const int m_off = (wid & 1) * 64;        // 2 m-groups x 64
    const int n_off = (wid >> 1) * 40;       // 4 n-groups x 40

    const int a_r = lane & 15;
    const int a_c = (lane >> 4) << 3;
    const int b_r = (lane & 7) + ((lane & 16) ? 8 : 0);
    const int b_c = (lane & 8) ? 8 : 0;
    const int b2_r = lane & 7;
    const int b2_c = (lane & 8) ? 8 : 0;

    const uint32_t mb = sbase + MBAR_OFF;    // full[s]=mb+s*16, empty=+8

    // stage chunk ch (sign = ch>>2, kb = (ch&3)*64) into slot ch%2
    auto stage_cp = [&](int ch) {
        const int sign = ch >> 2;
        const int kb   = (ch & 3) * 64;
        const uint32_t bufA = sbase + (ch & 1) * P_BUFB;
        const uint32_t bufB = bufA + P_ABYTES;
        // A: 2var x 128 rows x 8 granules = 2048 (8/thread)
        #pragma unroll
        for (int it = 0; it < 8; it++) {
            const int i = tid + it * 256;
            const int var = i >> 10;
            const int row = (i >> 3) & 127;
            const int g   = i & 7;
            cp16(bufA + (var * 128 + row) * (KLDA * 2) + g * 16,
                 g_A[sign * 2 + var] + (m0 + row) * HH + kb + g * 8);
        }
        // B: 2var x 160 rows x 8 granules = 2560 (10/thread, exact)
        #pragma unroll
        for (int it = 0; it < 10; it++) {
            const int i = tid + it * 256;            // 0..2559
            const int var = (i >= TN * 8) ? 1 : 0;
            const int jx  = i - var * TN * 8;
            const int row = jx >> 3;
            const int g   = jx & 7;
            cp16(bufB + (var * TN + row) * (KLDA * 2) + g * 16,
                 g_Bv[b][sign * 2 + var] + (n0 + row) * HH + kb + g * 8);
        }
    };

    if (tid < 2) {
        mbar_init(mb + tid * 16, 256);       // full[tid]
        mbar_init(mb + tid * 16 + 8, 8);     // empty[tid]
    }
    __syncthreads();

    // prologue: stage chunks 0..1
    #pragma unroll
    for (int c = 0; c < 2; c++) {
        stage_cp(c);
        cp_mbar_arrive_noinc(mb + c * 16);
    }

    float acc[4][5][4] = {};   // [mt 0..3][n8-tile 0..4][frag]

    for (int ch = 0; ch < 8; ch++) {
        const int s = ch & 1;
        const uint32_t par = (uint32_t)((ch >> 1) & 1);

        mbar_wait(mb + s * 16, par);

        const uint32_t bufA = sbase + s * P_BUFB;
        const uint32_t bufB = bufA + P_ABYTES;

        #pragma unroll
        for (int ks = 0; ks < 4; ks++) {
            uint32_t ah[4][4], al[4][4];
            #pragma unroll
            for (int mt = 0; mt < 4; mt++) {
                const uint32_t row = m_off + mt * 16 + a_r;
                const uint32_t col = ks * 16 + a_c;
                ldsm_x4(ah[mt], bufA + (row * KLDA + col) * 2);
                ldsm_x4(al[mt], bufA + ((128 + row) * KLDA + col) * 2);
            }
            uint32_t bh[2][4], bl[2][4], b2h[2], b2l[2];
            #pragma unroll
            for (int np = 0; np < 2; np++) {
                const uint32_t row = n_off + np * 16 + b_r;
                const uint32_t col = ks * 16 + b_c;
                ldsm_x4(bh[np], bufB + (row * KLDA + col) * 2);
                ldsm_x4(bl[np], bufB + ((TN + row) * KLDA + col) * 2);
            }
            {
                const uint32_t row = n_off + 32 + b2_r;
                const uint32_t col = ks * 16 + b2_c;
                ldsm_x2(b2h, bufB + (row * KLDA + col) * 2);
                ldsm_x2(b2l, bufB + ((TN + row) * KLDA + col) * 2);
            }
            // term-major: 20 independent accs between same-acc reuses
            #pragma unroll
            for (int mt = 0; mt < 4; mt++) {
                #pragma unroll
                for (int np = 0; np < 2; np++)
                    #pragma unroll
                    for (int nt = 0; nt < 2; nt++)
                        mma16816(acc[mt][np * 2 + nt], ah[mt],
                                 bh[np] + nt * 2);
                mma16816(acc[mt][4], ah[mt], b2h);
            }
            #pragma unroll
            for (int mt = 0; mt < 4; mt++) {
                #pragma unroll
                for (int np = 0; np < 2; np++)
                    #pragma unroll
                    for (int nt = 0; nt < 2; nt++)
                        mma16816(acc[mt][np * 2 + nt], ah[mt],
                                 bl[np] + nt * 2);
                mma16816(acc[mt][4], ah[mt], b2l);
            }
            #pragma unroll
            for (int mt = 0; mt < 4; mt++) {
                #pragma unroll
                for (int np = 0; np < 2; np++)
                    #pragma unroll
                    for (int nt = 0; nt < 2; nt++)
                        mma16816(acc[mt][np * 2 + nt], al[mt],
                                 bh[np] + nt * 2);
                mma16816(acc[mt][4], al[mt], b2h);
            }
        }

        if (lane == 0) mbar_arrive(mb + s * 16 + 8);

        // produce chunk ch+2 into slot s once ALL warps passed chunk ch
        if (ch + 2 < 8) {
            mbar_wait(mb + s * 16 + 8, par);
            stage_cp(ch + 2);
            cp_mbar_arrive_noinc(mb + s * 16);
        }
    }

    const int tg = lane >> 2, tig = lane & 3;
    #pragma unroll
    for (int mt = 0; mt < 4; mt++) {
        #pragma unroll
        for (int q = 0; q < 5; q++) {
            const int ncol = n0 + n_off + q * 8 + tig * 2;
            const int bin = ncol % NB;
            const float b0v = bo[bin];
            const float b1v = bo[bin + 1];
            const float* c = acc[mt][q];
            const int m = m0 + m_off + mt * 16 + tg;
            float* p0 = out + (size_t)m * (LL * NB) + ncol;
            *(float2*)p0 = make_float2(c[0] + b0v, c[1] + b1v);
            float* p1 = p0 + 8 * (size_t)(LL * NB);
            *(float2*)p1 = make_float2(c[2] + b0v, c[3] + b1v);
        }
    }
}

// ---------------------------------------------------------------------------
// launch
// ---------------------------------------------------------------------------
extern "C" void kernel_launch(void* const* d_in, const int* in_sizes, int n_in,
                              void* d_out, int out_size)
{
    const float* x  = (const float*)d_in[0];
    const float* Wi = (const float*)d_in[1];
    const float* bi = (const float*)d_in[2];
    const float* Wj = (const float*)d_in[3];
    const float* bj = (const float*)d_in[4];
    const float* Wo = (const float*)d_in[5];
    const float* bo = (const float*)d_in[6];
    float* out = (float*)d_out;

    prep_kernel<<<1600, 256>>>(x, Wi, Wj);

    cudaFuncSetAttribute(proj_mma_kernel,
                         cudaFuncAttributeMaxDynamicSharedMemorySize, PJ_SMEM);
    dim3 gA(6, 8, 3);
    proj_mma_kernel<<<gA, 256, PJ_SMEM>>>();

    postproj_kernel<<<768, 256>>>(bi, bj, Wo);

    cudaFuncSetAttribute(pair_mma_kernel,
                         cudaFuncAttributeMaxDynamicSharedMemorySize, PAIR_SMEM);
    dim3 gP(3840 / TN, 6);
    pair_mma_kernel<<<gP, 256, PAIR_SMEM>>>(bo, out);
}